// round 16
// baseline (speedup 1.0000x reference)
#include <cuda_runtime.h>
#include <cuda_bf16.h>
#include <math.h>
#include <stdint.h>

// ---------------------------------------------------------------------------
// DecoderLayer on GB300 (compute_100 PTX -> mma.sync HMMA everywhere).
// bf16 3-split GEMMs (64x64 warp tiles, swizzled smem) + split-K=2 for the
// N=768 GEMMs + bf16 3-split flash attention (BQ=128, 2 CTAs/SM via
// launch_bounds + K/V register reuse). fp32 LN.
// B=8, S=1024, D=768, H=12, Dh=64, DFF=3072.
// ---------------------------------------------------------------------------
#define BATCH   8
#define SEQ     1024
#define DMODEL  768
#define NHEADS  12
#define DHEAD   64
#define DFF     3072
#define MROWS   (BATCH*SEQ)          // 8192

typedef __nv_bfloat16 bf16;

// ------------------------- scratch (device globals) -------------------------
__device__ bf16  g_xh  [MROWS*DMODEL],   g_xl  [MROWS*DMODEL];
__device__ bf16  g_wqkvh[3*DMODEL*DMODEL], g_wqkvl[3*DMODEL*DMODEL]; // [2304,768]
__device__ bf16  g_woh [DMODEL*DMODEL],  g_wol [DMODEL*DMODEL];
__device__ bf16  g_w1h [DFF*DMODEL],     g_w1l [DFF*DMODEL];
__device__ bf16  g_w2h [DMODEL*DFF],     g_w2l [DMODEL*DFF];
__device__ float g_bqkv[3*DMODEL];
__device__ bf16  g_qkvh[3*MROWS*DMODEL], g_qkvl[3*MROWS*DMODEL];  // [which][b,h,s,d]
__device__ bf16  g_ch  [MROWS*DMODEL],   g_cl  [MROWS*DMODEL];    // ctx hi/lo
__device__ float g_attn[MROWS*DMODEL];   // split-K partial 0
__device__ float g_p2  [MROWS*DMODEL];   // split-K partial 1
__device__ float g_out1[MROWS*DMODEL];
__device__ bf16  g_o1h [MROWS*DMODEL],   g_o1l [MROWS*DMODEL];
__device__ bf16  g_h1h [MROWS*DFF],      g_h1l [MROWS*DFF];
__device__ float g_ffn [MROWS*DMODEL];   // split-K partial 0 (FFN2)

// ------------------------------ PTX helpers ---------------------------------
__device__ __forceinline__ uint32_t smem_u32(const void* p) {
    uint32_t a;
    asm("{ .reg .u64 t; cvta.to.shared.u64 t, %1; cvt.u32.u64 %0, t; }"
        : "=r"(a) : "l"(p));
    return a;
}

#define CP16(dst, src) \
    asm volatile("cp.async.cg.shared.global [%0], [%1], 16;" \
                 :: "r"(dst), "l"(src))
#define CP_COMMIT() asm volatile("cp.async.commit_group;" ::: "memory")
#define CP_WAIT(n)  asm volatile("cp.async.wait_group %0;" :: "n"(n) : "memory")

#define LDM_X4(r, a) \
    asm volatile("ldmatrix.sync.aligned.m8n8.x4.shared.b16 {%0,%1,%2,%3}, [%4];" \
        : "=r"((r)[0]), "=r"((r)[1]), "=r"((r)[2]), "=r"((r)[3]) : "r"(a))

#define LDM_X4T(r, a) \
    asm volatile("ldmatrix.sync.aligned.m8n8.x4.trans.shared.b16 {%0,%1,%2,%3}, [%4];" \
        : "=r"((r)[0]), "=r"((r)[1]), "=r"((r)[2]), "=r"((r)[3]) : "r"(a))

#define MMA16816(d, a, b0, b1) \
    asm volatile("mma.sync.aligned.m16n8k16.row.col.f32.bf16.bf16.f32 " \
        "{%0,%1,%2,%3}, {%4,%5,%6,%7}, {%8,%9}, {%0,%1,%2,%3};" \
        : "+f"((d)[0]), "+f"((d)[1]), "+f"((d)[2]), "+f"((d)[3]) \
        : "r"((a)[0]), "r"((a)[1]), "r"((a)[2]), "r"((a)[3]), "r"(b0), "r"(b1))

__device__ __forceinline__ void split2(float x, float y, uint32_t& hp, uint32_t& lp) {
    __nv_bfloat162 h = __float22bfloat162_rn(make_float2(x, y));
    float2 r = make_float2(x - __bfloat162float(h.x), y - __bfloat162float(h.y));
    __nv_bfloat162 l = __float22bfloat162_rn(r);
    hp = *(uint32_t*)&h;
    lp = *(uint32_t*)&l;
}

// ---------------------- HMMA GEMM: C = A @ B^T + bias -----------------------
// CTA tile BM=128 x BN=256, BK=64. 256 threads = 8 warps (2 x 4),
// warp tile 64x64. Swizzled 128B-row smem (seg ^= row&7). B-register reuse.
// Split-K via gridDim.z (EPI==0 only): kz=0 -> Cf (+bias), kz=1 -> Cf2.
// EPI: 0 = fp32 [M,N]; 2 = ReLU + bf16 hi/lo [M,N]; 3 = QKV bf16 hi/lo scatter.
#define GA_BYTES 16384               // one A array: 128 rows x 128 B
#define GB_BYTES 32768               // one B array: 256 rows x 128 B
#define GSTG     (2*GA_BYTES + 2*GB_BYTES)   // 98304 B per stage
#define GSMEM    (2 * GSTG)                  // 196608 B

template<int EPI>
__global__ void __launch_bounds__(256, 1)
mma_gemm(const bf16* __restrict__ Ah_, const bf16* __restrict__ Al_,
         const bf16* __restrict__ Bh_, const bf16* __restrict__ Bl_,
         const float* __restrict__ bias,
         float* __restrict__ Cf, float* __restrict__ Cf2,
         bf16* __restrict__ Ch, bf16* __restrict__ Cl,
         int N, int K)
{
    extern __shared__ __align__(128) char smem[];
    const uint32_t sb = smem_u32(smem);
    const int tid  = threadIdx.x;
    const int lane = tid & 31;
    const int wid  = tid >> 5;
    const int wm   = wid >> 2;            // 0..1  (64-row band)
    const int wn   = wid & 3;             // 0..3  (64-col band)
    const int row0 = blockIdx.y * 128, col0 = blockIdx.x * 256;
    const int kz   = blockIdx.z;
    const int Kp   = K / (int)gridDim.z;  // K per slice
    const int kbeg = kz * Kp;
    const int NT   = Kp >> 6;             // BK = 64

    float acc[4][8][4];
#pragma unroll
    for (int i = 0; i < 4; i++)
#pragma unroll
        for (int j = 0; j < 8; j++)
#pragma unroll
            for (int r = 0; r < 4; r++) acc[i][j][r] = 0.f;

    auto load_stage = [&](int kt, int stg) {
        const int k0 = kbeg + (kt << 6);
        const uint32_t sd = sb + stg * GSTG;
#pragma unroll
        for (int c = tid; c < 6144; c += 256) {
            if (c < 2048) {               // A arrays
                const int arr = c >> 10, rem = c & 1023;
                const int r = rem >> 3, seg = rem & 7;
                const uint32_t d = sd + arr * GA_BYTES + r * 128
                                 + ((seg ^ (r & 7)) << 4);
                const bf16* s = (arr ? Al_ : Ah_) + (size_t)(row0 + r) * K + k0 + seg * 8;
                CP16(d, s);
            } else {                      // B arrays
                const int cc = c - 2048;
                const int arr = cc >> 11, rem = cc & 2047;
                const int r = rem >> 3, seg = rem & 7;
                const uint32_t d = sd + 2 * GA_BYTES + arr * GB_BYTES + r * 128
                                 + ((seg ^ (r & 7)) << 4);
                const bf16* s = (arr ? Bl_ : Bh_) + (size_t)(col0 + r) * K + k0 + seg * 8;
                CP16(d, s);
            }
        }
    };

    load_stage(0, 0); CP_COMMIT();

    for (int kt = 0; kt < NT; kt++) {
        CP_WAIT(0);
        __syncthreads();
        if (kt + 1 < NT) {
            load_stage(kt + 1, (kt + 1) & 1);
            CP_COMMIT();
        }

        const uint32_t sA = sb + (kt & 1) * GSTG;
        const uint32_t sB = sA + 2 * GA_BYTES;
#pragma unroll
        for (int kc = 0; kc < 4; kc++) {   // four K16 slices
            uint32_t ah[4][4], al[4][4], b[4][4];
            uint32_t baddr[4];
#pragma unroll
            for (int mt = 0; mt < 4; mt++) {
                const int row = wm * 64 + mt * 16 + (lane & 15);
                const int seg = kc * 2 + (lane >> 4);
                const uint32_t a = sA + (uint32_t)(row * 128 + ((seg ^ (row & 7)) << 4));
                LDM_X4(ah[mt], a);
                LDM_X4(al[mt], a + GA_BYTES);
            }
#pragma unroll
            for (int g = 0; g < 4; g++) {
                const int row = wn * 64 + g * 16 + ((lane >> 4) << 3) + (lane & 7);
                const int seg = kc * 2 + ((lane >> 3) & 1);
                baddr[g] = sB + (uint32_t)(row * 128 + ((seg ^ (row & 7)) << 4));
                LDM_X4(b[g], baddr[g]);             // Bh
            }
            // terms 1 + 3 use Bh
#pragma unroll
            for (int mt = 0; mt < 4; mt++)
#pragma unroll
                for (int nt = 0; nt < 8; nt++) {
                    const int g = nt >> 1, o = (nt & 1) * 2;
                    MMA16816(acc[mt][nt], ah[mt], b[g][o], b[g][o + 1]);
                }
#pragma unroll
            for (int mt = 0; mt < 4; mt++)
#pragma unroll
                for (int nt = 0; nt < 8; nt++) {
                    const int g = nt >> 1, o = (nt & 1) * 2;
                    MMA16816(acc[mt][nt], al[mt], b[g][o], b[g][o + 1]);
                }
            // reload same registers with Bl, term 2
#pragma unroll
            for (int g = 0; g < 4; g++)
                LDM_X4(b[g], baddr[g] + GB_BYTES);  // Bl
#pragma unroll
            for (int mt = 0; mt < 4; mt++)
#pragma unroll
                for (int nt = 0; nt < 8; nt++) {
                    const int g = nt >> 1, o = (nt & 1) * 2;
                    MMA16816(acc[mt][nt], ah[mt], b[g][o], b[g][o + 1]);
                }
        }
    }

    // ---- epilogue straight from registers ----
    float* dst = (EPI == 0 && kz) ? Cf2 : Cf;
#pragma unroll
    for (int mt = 0; mt < 4; mt++) {
#pragma unroll
        for (int nt = 0; nt < 8; nt++) {
            const int row = row0 + wm * 64 + mt * 16 + (lane >> 2);
            const int col = col0 + wn * 64 + nt * 8 + (lane & 3) * 2;
            const bool wbias = (EPI != 0) || (kz == 0);
            const float b0 = wbias ? __ldg(bias + col)     : 0.f;
            const float b1 = wbias ? __ldg(bias + col + 1) : 0.f;
#pragma unroll
            for (int half = 0; half < 2; half++) {
                const int rr = row + half * 8;
                float v0 = acc[mt][nt][half * 2]     + b0;
                float v1 = acc[mt][nt][half * 2 + 1] + b1;
                if (EPI == 0) {
                    *(float2*)&dst[(size_t)rr * N + col] = make_float2(v0, v1);
                } else if (EPI == 2) {
                    v0 = fmaxf(v0, 0.f); v1 = fmaxf(v1, 0.f);
                    uint32_t hp, lp;
                    split2(v0, v1, hp, lp);
                    *(uint32_t*)&Ch[(size_t)rr * N + col] = hp;
                    *(uint32_t*)&Cl[(size_t)rr * N + col] = lp;
                } else {  // EPI==3: QKV scatter [which][b,h,s,d], Q pre-scaled
                    const int which = col / DMODEL;
                    const int cc = col - which * DMODEL;
                    const int h = cc >> 6, d = cc & 63;
                    if (which == 0) { v0 *= 0.125f; v1 *= 0.125f; }
                    const int b_ = rr >> 10, s = rr & 1023;
                    const size_t dsti = (size_t)which * MROWS * DMODEL
                        + (((size_t)(b_ * NHEADS + h)) * SEQ + s) * DHEAD + d;
                    uint32_t hp, lp;
                    split2(v0, v1, hp, lp);
                    *(uint32_t*)&Ch[dsti] = hp;
                    *(uint32_t*)&Cl[dsti] = lp;
                }
            }
        }
    }
}

// ---------------------- flash attention (HMMA bf16 3-split) ------------------
// BQ=128, BK=64. 256 threads = 8 warps. launch_bounds(256,2) -> 2 CTAs/SM
// (221 KB smem of 228 KB pool), 4 warps/SMSP. K/V fragments loaded twice into
// single register buffers (hi -> two terms, lo -> one) to fit 128 regs.
// Heavy q-tiles launched first (qt reversed).
#define ASTR   72
#define QTILE  (128 * ASTR * 2)       // 18432 B per Q array
#define KVTILE (64 * ASTR * 2)        // 9216 B per KV array
#define AKVST  (4 * KVTILE)           // 36864 B per stage
#define ATT_SMEM (2 * QTILE + 2 * AKVST)   // 110592 B

__global__ void __launch_bounds__(256, 2)
attn_mma(const bf16* __restrict__ QKVh, const bf16* __restrict__ QKVl,
         bf16* __restrict__ ch, bf16* __restrict__ cl)
{
    extern __shared__ __align__(128) char smem[];
    const uint32_t sb = smem_u32(smem);
    const int tid = threadIdx.x, lane = tid & 31, wid = tid >> 5;
    const int qt = (int)gridDim.x - 1 - (int)blockIdx.x;   // heavy first
    const int bh = blockIdx.y, q0 = qt * 128;
    const int NKT = 2 * qt + 2;
    constexpr size_t MD = (size_t)MROWS * DMODEL;
    const bf16 *Qh = QKVh,        *Kh = QKVh + MD, *Vh = QKVh + 2 * MD;
    const bf16 *Ql = QKVl,        *Kl = QKVl + MD, *Vl = QKVl + 2 * MD;
    const size_t hb = (size_t)bh * SEQ * DHEAD;

    auto load_kv = [&](int kt, int stg) {
        const size_t gb = hb + (size_t)(kt * 64) * 64;
        const uint32_t sd = sb + 2 * QTILE + stg * AKVST;
        for (int i = tid; i < 512; i += 256) {
            const int row = i >> 3, seg = i & 7;
            const uint32_t d0 = sd + row * 144 + seg * 16;
            const size_t g = gb + row * 64 + seg * 8;
            CP16(d0,              Kh + g);
            CP16(d0 + KVTILE,     Kl + g);
            CP16(d0 + 2 * KVTILE, Vh + g);
            CP16(d0 + 3 * KVTILE, Vl + g);
        }
    };

    {   // Q tiles (128 rows) + stage0
        const size_t gq = hb + (size_t)q0 * 64;
        for (int i = tid; i < 1024; i += 256) {
            const int row = i >> 3, seg = i & 7;
            const uint32_t d0 = sb + row * 144 + seg * 16;
            const size_t g = gq + row * 64 + seg * 8;
            CP16(d0,         Qh + g);
            CP16(d0 + QTILE, Ql + g);
        }
        load_kv(0, 0);
    }
    CP_COMMIT();
    load_kv(1, 1);
    CP_COMMIT();

    uint32_t qh[4][4], ql[4][4];
    float oacc[8][4];
#pragma unroll
    for (int nt = 0; nt < 8; nt++)
#pragma unroll
        for (int e = 0; e < 4; e++) oacc[nt][e] = 0.f;
    float m0 = -1e30f, m1 = -1e30f, l0 = 0.f, l1 = 0.f;

    const int lcol  = (lane & 3) * 2;
    const int rowg0 = q0 + wid * 16 + (lane >> 2);
    const int wrow_max = q0 + wid * 16 + 15;

    for (int kt = 0; kt < NKT; kt++) {
        CP_WAIT(1);
        __syncthreads();
        if (kt == 0) {
#pragma unroll
            for (int kc = 0; kc < 4; kc++) {
                const uint32_t a = sb + (uint32_t)(((wid * 16 + (lane & 15)) * ASTR
                                    + ((lane >> 4) << 3) + kc * 16) * 2);
                LDM_X4(qh[kc], a);
                LDM_X4(ql[kc], a + QTILE);
            }
        }
        const bool active = (kt * 64 <= wrow_max);
        const uint32_t kvb = sb + 2 * QTILE + (kt & 1) * AKVST;

        if (active) {
            float sacc[8][4];
#pragma unroll
            for (int nt = 0; nt < 8; nt++)
#pragma unroll
                for (int e = 0; e < 4; e++) sacc[nt][e] = 0.f;

#pragma unroll
            for (int kc = 0; kc < 4; kc++) {
                uint32_t k2[8][2];
                uint32_t kaddr[4];
#pragma unroll
                for (int g = 0; g < 4; g++) {
                    kaddr[g] = kvb + (uint32_t)(((g * 16 + ((lane >> 4) << 3)
                        + (lane & 7)) * ASTR + (((lane >> 3) & 1) << 3) + kc * 16) * 2);
                    uint32_t r[4];
                    LDM_X4(r, kaddr[g]);            // Kh
                    k2[2*g][0]=r[0]; k2[2*g][1]=r[1]; k2[2*g+1][0]=r[2]; k2[2*g+1][1]=r[3];
                }
#pragma unroll
                for (int nt = 0; nt < 8; nt++)
                    MMA16816(sacc[nt], qh[kc], k2[nt][0], k2[nt][1]);   // Qh.Kh
#pragma unroll
                for (int nt = 0; nt < 8; nt++)
                    MMA16816(sacc[nt], ql[kc], k2[nt][0], k2[nt][1]);   // Ql.Kh
#pragma unroll
                for (int g = 0; g < 4; g++) {
                    uint32_t r[4];
                    LDM_X4(r, kaddr[g] + KVTILE);   // Kl
                    k2[2*g][0]=r[0]; k2[2*g][1]=r[1]; k2[2*g+1][0]=r[2]; k2[2*g+1][1]=r[3];
                }
#pragma unroll
                for (int nt = 0; nt < 8; nt++)
                    MMA16816(sacc[nt], qh[kc], k2[nt][0], k2[nt][1]);   // Qh.Kl
            }

            if (kt * 64 + 63 > rowg0) {
#pragma unroll
                for (int nt = 0; nt < 8; nt++) {
                    const int colb = kt * 64 + nt * 8 + lcol;
                    if (colb     > rowg0)     sacc[nt][0] = -1e30f;
                    if (colb + 1 > rowg0)     sacc[nt][1] = -1e30f;
                    if (colb     > rowg0 + 8) sacc[nt][2] = -1e30f;
                    if (colb + 1 > rowg0 + 8) sacc[nt][3] = -1e30f;
                }
            }

            float tm0 = -1e30f, tm1 = -1e30f;
#pragma unroll
            for (int nt = 0; nt < 8; nt++) {
                tm0 = fmaxf(tm0, fmaxf(sacc[nt][0], sacc[nt][1]));
                tm1 = fmaxf(tm1, fmaxf(sacc[nt][2], sacc[nt][3]));
            }
            tm0 = fmaxf(tm0, __shfl_xor_sync(0xffffffffu, tm0, 1));
            tm0 = fmaxf(tm0, __shfl_xor_sync(0xffffffffu, tm0, 2));
            tm1 = fmaxf(tm1, __shfl_xor_sync(0xffffffffu, tm1, 1));
            tm1 = fmaxf(tm1, __shfl_xor_sync(0xffffffffu, tm1, 2));

            const float mn0 = fmaxf(m0, tm0), mn1 = fmaxf(m1, tm1);
            const float a0 = __expf(m0 - mn0), a1 = __expf(m1 - mn1);
            m0 = mn0; m1 = mn1;

            float s0 = 0.f, s1 = 0.f;
#pragma unroll
            for (int nt = 0; nt < 8; nt++) {
                sacc[nt][0] = __expf(sacc[nt][0] - mn0); s0 += sacc[nt][0];
                sacc[nt][1] = __expf(sacc[nt][1] - mn0); s0 += sacc[nt][1];
                sacc[nt][2] = __expf(sacc[nt][2] - mn1); s1 += sacc[nt][2];
                sacc[nt][3] = __expf(sacc[nt][3] - mn1); s1 += sacc[nt][3];
            }
            s0 += __shfl_xor_sync(0xffffffffu, s0, 1);
            s0 += __shfl_xor_sync(0xffffffffu, s0, 2);
            s1 += __shfl_xor_sync(0xffffffffu, s1, 1);
            s1 += __shfl_xor_sync(0xffffffffu, s1, 2);
            l0 = l0 * a0 + s0;
            l1 = l1 * a1 + s1;
#pragma unroll
            for (int nt = 0; nt < 8; nt++) {
                oacc[nt][0] *= a0; oacc[nt][1] *= a0;
                oacc[nt][2] *= a1; oacc[nt][3] *= a1;
            }

            const uint32_t vb = kvb + 2 * KVTILE;
#pragma unroll
            for (int j = 0; j < 4; j++) {
                uint32_t v2[8][2];
                uint32_t vaddr[4];
#pragma unroll
                for (int ng = 0; ng < 4; ng++) {
                    vaddr[ng] = vb + (uint32_t)(((j * 16 + (lane & 15)) * ASTR
                                    + ng * 16 + ((lane >> 4) << 3)) * 2);
                    uint32_t r[4];
                    LDM_X4T(r, vaddr[ng]);          // Vh
                    v2[2*ng][0]=r[0]; v2[2*ng][1]=r[1]; v2[2*ng+1][0]=r[2]; v2[2*ng+1][1]=r[3];
                }
                uint32_t ph[4], pl[4];
                split2(sacc[2*j][0],   sacc[2*j][1],   ph[0], pl[0]);
                split2(sacc[2*j][2],   sacc[2*j][3],   ph[1], pl[1]);
                split2(sacc[2*j+1][0], sacc[2*j+1][1], ph[2], pl[2]);
                split2(sacc[2*j+1][2], sacc[2*j+1][3], ph[3], pl[3]);
#pragma unroll
                for (int nt = 0; nt < 8; nt++)
                    MMA16816(oacc[nt], ph, v2[nt][0], v2[nt][1]);       // Ph.Vh
#pragma unroll
                for (int nt = 0; nt < 8; nt++)
                    MMA16816(oacc[nt], pl, v2[nt][0], v2[nt][1]);       // Pl.Vh
#pragma unroll
                for (int ng = 0; ng < 4; ng++) {
                    uint32_t r[4];
                    LDM_X4T(r, vaddr[ng] + KVTILE); // Vl
                    v2[2*ng][0]=r[0]; v2[2*ng][1]=r[1]; v2[2*ng+1][0]=r[2]; v2[2*ng+1][1]=r[3];
                }
#pragma unroll
                for (int nt = 0; nt < 8; nt++)
                    MMA16816(oacc[nt], ph, v2[nt][0], v2[nt][1]);       // Ph.Vl
            }
        }
        __syncthreads();
        if (kt + 2 < NKT) load_kv(kt + 2, kt & 1);
        CP_COMMIT();
    }

    const float i0 = 1.f / l0, i1 = 1.f / l1;
    const int b_ = bh / NHEADS, h = bh % NHEADS;
#pragma unroll
    for (int nt = 0; nt < 8; nt++) {
        const int d = nt * 8 + lcol;
        const size_t r0i = ((size_t)(b_ * SEQ + rowg0)) * DMODEL + h * 64 + d;
        const size_t r1i = r0i + (size_t)8 * DMODEL;
        uint32_t hp, lp;
        split2(oacc[nt][0] * i0, oacc[nt][1] * i0, hp, lp);
        *(uint32_t*)&ch[r0i] = hp;
        *(uint32_t*)&cl[r0i] = lp;
        split2(oacc[nt][2] * i1, oacc[nt][3] * i1, hp, lp);
        *(uint32_t*)&ch[r1i] = hp;
        *(uint32_t*)&cl[r1i] = lp;
    }
}

// ---------------------- prep kernels ----------------------------------------
__global__ void __launch_bounds__(256)
split_kernel(const float* __restrict__ src, bf16* __restrict__ hi,
             bf16* __restrict__ lo, int n)
{
    int i0 = (blockIdx.x * 256 + threadIdx.x) * 4;
    if (i0 >= n) return;
#pragma unroll
    for (int j = 0; j < 4; j++) {
        float v = src[i0 + j];
        bf16 h = __float2bfloat16(v);
        hi[i0 + j] = h;
        lo[i0 + j] = __float2bfloat16(v - __bfloat162float(h));
    }
}

// Fused transpose+split of ALL weights: src[K,N] -> dst[N,K] bf16 hi/lo.
__global__ void __launch_bounds__(256)
prep_weights(const float* __restrict__ wq, const float* __restrict__ wk,
             const float* __restrict__ wv, const float* __restrict__ wo,
             const float* __restrict__ w1, const float* __restrict__ w2,
             bf16* __restrict__ wqkvh, bf16* __restrict__ wqkvl,
             bf16* __restrict__ woh,   bf16* __restrict__ wol,
             bf16* __restrict__ w1h,   bf16* __restrict__ w1l,
             bf16* __restrict__ w2h,   bf16* __restrict__ w2l)
{
    int b = blockIdx.x;
    const float* src; bf16 *dh, *dl; int K, N;
    if (b < 1728) {
        const int w = b / 576; b -= w * 576;
        src = (w == 0) ? wq : (w == 1 ? wk : wv);
        dh = wqkvh + (size_t)w * DMODEL * DMODEL;
        dl = wqkvl + (size_t)w * DMODEL * DMODEL;
        K = DMODEL; N = DMODEL;
    } else if (b < 2304) { b -= 1728; src = wo; dh = woh; dl = wol; K = DMODEL; N = DMODEL; }
    else if (b < 4608)   { b -= 2304; src = w1; dh = w1h; dl = w1l; K = DMODEL; N = DFF; }
    else                 { b -= 4608; src = w2; dh = w2h; dl = w2l; K = DFF; N = DMODEL; }

    const int nb = N / 32;
    const int bx = (b % nb) * 32;
    const int by = (b / nb) * 32;
    __shared__ float t[32][33];
    const int tx = threadIdx.x & 31, ty = threadIdx.x >> 5;
#pragma unroll
    for (int i = 0; i < 32; i += 8)
        t[ty + i][tx] = src[(size_t)(by + ty + i) * N + bx + tx];
    __syncthreads();
#pragma unroll
    for (int i = 0; i < 32; i += 8) {
        float v = t[tx][ty + i];
        bf16 h = __float2bfloat16(v);
        size_t o = (size_t)(bx + ty + i) * K + by + tx;
        dh[o] = h;
        dl[o] = __float2bfloat16(v - __bfloat162float(h));
    }
}

__global__ void __launch_bounds__(256)
concat_bias(const float* __restrict__ bq, const float* __restrict__ bk,
            const float* __restrict__ bv, float* __restrict__ out)
{
    int i = blockIdx.x * 256 + threadIdx.x;
    if (i >= 3 * DMODEL) return;
    out[i] = i < DMODEL ? bq[i] : (i < 2 * DMODEL ? bk[i - DMODEL] : bv[i - 2 * DMODEL]);
}

// ------------- fused residual add + split-K reduce + LayerNorm --------------
// out = LN(a + p0 + p1), optional bf16 hi/lo output.
template<bool HILO>
__global__ void __launch_bounds__(256)
add_ln3_kernel(const float* __restrict__ a, const float* __restrict__ p0,
               const float* __restrict__ p1,
               const float* __restrict__ g, const float* __restrict__ be,
               float* __restrict__ out, bf16* __restrict__ ohi, bf16* __restrict__ olo)
{
    __shared__ float red[8];
    const int row = blockIdx.x;
    const int t   = threadIdx.x;
    const float* ar = a  + (size_t)row * DMODEL;
    const float* b0 = p0 + (size_t)row * DMODEL;
    const float* b1 = p1 + (size_t)row * DMODEL;

    float v0 = ar[t]       + b0[t]       + b1[t];
    float v1 = ar[t + 256] + b0[t + 256] + b1[t + 256];
    float v2 = ar[t + 512] + b0[t + 512] + b1[t + 512];

    float sum = v0 + v1 + v2;
#pragma unroll
    for (int off = 16; off; off >>= 1) sum += __shfl_xor_sync(0xffffffffu, sum, off);
    if ((t & 31) == 0) red[t >> 5] = sum;
    __syncthreads();
    float tot = 0.f;
#pragma unroll
    for (int w = 0; w < 8; w++) tot += red[w];
    const float mu = tot * (1.f / DMODEL);
    __syncthreads();

    float d0 = v0 - mu, d1 = v1 - mu, d2 = v2 - mu;
    float vs = d0 * d0 + d1 * d1 + d2 * d2;
#pragma unroll
    for (int off = 16; off; off >>= 1) vs += __shfl_xor_sync(0xffffffffu, vs, off);
    if ((t & 31) == 0) red[t >> 5] = vs;
    __syncthreads();
    tot = 0.f;
#pragma unroll
    for (int w = 0; w < 8; w++) tot += red[w];
    const float rstd = rsqrtf(tot * (1.f / DMODEL) + 1e-6f);

    float* o = out + (size_t)row * DMODEL;
    float r0 = g[t]       * d0 * rstd + be[t];
    float r1 = g[t + 256] * d1 * rstd + be[t + 256];
    float r2 = g[t + 512] * d2 * rstd + be[t + 512];
    o[t] = r0; o[t + 256] = r1; o[t + 512] = r2;
    if (HILO) {
        size_t base = (size_t)row * DMODEL;
#pragma unroll
        for (int j = 0; j < 3; j++) {
            float v = j == 0 ? r0 : (j == 1 ? r1 : r2);
            int idx = t + j * 256;
            bf16 h = __float2bfloat16(v);
            ohi[base + idx] = h;
            olo[base + idx] = __float2bfloat16(v - __bfloat162float(h));
        }
    }
}

// --------------------------------- launch ------------------------------------
extern "C" void kernel_launch(void* const* d_in, const int* in_sizes, int n_in,
                              void* d_out, int out_size)
{
    const float* x  = (const float*)d_in[0];
    const float* wq = (const float*)d_in[2];
    const float* bq = (const float*)d_in[3];
    const float* wk = (const float*)d_in[4];
    const float* bk = (const float*)d_in[5];
    const float* wv = (const float*)d_in[6];
    const float* bv = (const float*)d_in[7];
    const float* wo = (const float*)d_in[8];
    const float* bo = (const float*)d_in[9];
    const float* w1 = (const float*)d_in[10];
    const float* b1 = (const float*)d_in[11];
    const float* w2 = (const float*)d_in[12];
    const float* b2 = (const float*)d_in[13];
    const float* g1 = (const float*)d_in[14];
    const float* be1= (const float*)d_in[15];
    const float* g2 = (const float*)d_in[16];
    const float* be2= (const float*)d_in[17];
    float* out = (float*)d_out;

    bf16 *xh,*xl,*wqkvh,*wqkvl,*woh,*wol,*w1h,*w1l,*w2h,*w2l;
    bf16 *qkvh,*qkvl,*ch,*cl,*o1h,*o1l,*h1h,*h1l;
    float *bqkv,*attn,*p2,*out1,*ffn;
    cudaGetSymbolAddress((void**)&xh,   g_xh);    cudaGetSymbolAddress((void**)&xl,   g_xl);
    cudaGetSymbolAddress((void**)&wqkvh,g_wqkvh); cudaGetSymbolAddress((void**)&wqkvl,g_wqkvl);
    cudaGetSymbolAddress((void**)&woh,  g_woh);   cudaGetSymbolAddress((void**)&wol,  g_wol);
    cudaGetSymbolAddress((void**)&w1h,  g_w1h);   cudaGetSymbolAddress((void**)&w1l,  g_w1l);
    cudaGetSymbolAddress((void**)&w2h,  g_w2h);   cudaGetSymbolAddress((void**)&w2l,  g_w2l);
    cudaGetSymbolAddress((void**)&bqkv, g_bqkv);
    cudaGetSymbolAddress((void**)&qkvh, g_qkvh);  cudaGetSymbolAddress((void**)&qkvl, g_qkvl);
    cudaGetSymbolAddress((void**)&ch,   g_ch);    cudaGetSymbolAddress((void**)&cl,   g_cl);
    cudaGetSymbolAddress((void**)&o1h,  g_o1h);   cudaGetSymbolAddress((void**)&o1l,  g_o1l);
    cudaGetSymbolAddress((void**)&h1h,  g_h1h);   cudaGetSymbolAddress((void**)&h1l,  g_h1l);
    cudaGetSymbolAddress((void**)&attn, g_attn);  cudaGetSymbolAddress((void**)&p2,   g_p2);
    cudaGetSymbolAddress((void**)&out1, g_out1);  cudaGetSymbolAddress((void**)&ffn,  g_ffn);

    cudaFuncSetAttribute(mma_gemm<0>, cudaFuncAttributeMaxDynamicSharedMemorySize, GSMEM);
    cudaFuncSetAttribute(mma_gemm<2>, cudaFuncAttributeMaxDynamicSharedMemorySize, GSMEM);
    cudaFuncSetAttribute(mma_gemm<3>, cudaFuncAttributeMaxDynamicSharedMemorySize, GSMEM);
    cudaFuncSetAttribute(attn_mma,    cudaFuncAttributeMaxDynamicSharedMemorySize, ATT_SMEM);

    // ---- prep ----
    split_kernel<<<MROWS * DMODEL / 1024, 256>>>(x, xh, xl, MROWS * DMODEL);   // #1
    prep_weights<<<6912, 256>>>(wq, wk, wv, wo, w1, w2,
                                wqkvh, wqkvl, woh, wol, w1h, w1l, w2h, w2l);   // #2
    concat_bias<<<(3*DMODEL + 255)/256, 256>>>(bq, bk, bv, bqkv);              // #3

    // ---- fused QKV (N=2304), epilogue -> bf16 hi/lo head layout ----
    mma_gemm<3><<<dim3(3*DMODEL/256, MROWS/128), 256, GSMEM>>>(
        xh, xl, wqkvh, wqkvl, bqkv, nullptr, nullptr, qkvh, qkvl, 3*DMODEL, DMODEL); // #4

    // ---- flash attention (BQ=128, 2 CTAs/SM, heavy tiles first) ----
    attn_mma<<<dim3(SEQ/128, BATCH*NHEADS), 256, ATT_SMEM>>>(qkvh, qkvl, ch, cl);    // #5

    // ---- O proj: split-K=2 (partials attn, p2) + LN1 reduce ----
    mma_gemm<0><<<dim3(DMODEL/256, MROWS/128, 2), 256, GSMEM>>>(
        ch, cl, woh, wol, bo, attn, p2, nullptr, nullptr, DMODEL, DMODEL);     // #6
    add_ln3_kernel<true><<<MROWS, 256>>>(x, attn, p2, g1, be1, out1, o1h, o1l);

    // ---- FFN ----
    mma_gemm<2><<<dim3(DFF/256, MROWS/128), 256, GSMEM>>>(o1h, o1l, w1h, w1l, b1,
                                                          nullptr, nullptr, h1h, h1l,
                                                          DFF, DMODEL);
    // FFN2: split-K=2 (partials ffn, p2) + LN2 reduce
    mma_gemm<0><<<dim3(DMODEL/256, MROWS/128, 2), 256, GSMEM>>>(
        h1h, h1l, w2h, w2l, b2, ffn, p2, nullptr, nullptr, DMODEL, DFF);
    add_ln3_kernel<false><<<MROWS, 256>>>(out1, ffn, p2, g2, be2, out, nullptr, nullptr);
}

// round 17
// speedup vs baseline: 1.0248x; 1.0248x over previous
#include <cuda_runtime.h>
#include <cuda_bf16.h>
#include <math.h>
#include <stdint.h>

// ---------------------------------------------------------------------------
// DecoderLayer on GB300 (compute_100 PTX -> mma.sync HMMA everywhere).
// bf16 3-split GEMMs (64x64 warp tiles, swizzled smem) + split-K=3 for the
// N=768 GEMMs (wave-quantization fix; reduce fused into add_ln4) +
// bf16 3-split flash attention (BQ=128). fp32 LN.
// B=8, S=1024, D=768, H=12, Dh=64, DFF=3072.
// ---------------------------------------------------------------------------
#define BATCH   8
#define SEQ     1024
#define DMODEL  768
#define NHEADS  12
#define DHEAD   64
#define DFF     3072
#define MROWS   (BATCH*SEQ)          // 8192

typedef __nv_bfloat16 bf16;

// ------------------------- scratch (device globals) -------------------------
__device__ bf16  g_xh  [MROWS*DMODEL],   g_xl  [MROWS*DMODEL];
__device__ bf16  g_wqkvh[3*DMODEL*DMODEL], g_wqkvl[3*DMODEL*DMODEL]; // [2304,768]
__device__ bf16  g_woh [DMODEL*DMODEL],  g_wol [DMODEL*DMODEL];
__device__ bf16  g_w1h [DFF*DMODEL],     g_w1l [DFF*DMODEL];
__device__ bf16  g_w2h [DMODEL*DFF],     g_w2l [DMODEL*DFF];
__device__ float g_bqkv[3*DMODEL];
__device__ bf16  g_qkvh[3*MROWS*DMODEL], g_qkvl[3*MROWS*DMODEL];  // [which][b,h,s,d]
__device__ bf16  g_ch  [MROWS*DMODEL],   g_cl  [MROWS*DMODEL];    // ctx hi/lo
__device__ float g_attn[MROWS*DMODEL];   // split-K partial 0
__device__ float g_p2  [MROWS*DMODEL];   // split-K partial 1
__device__ float g_p3  [MROWS*DMODEL];   // split-K partial 2
__device__ float g_out1[MROWS*DMODEL];
__device__ bf16  g_o1h [MROWS*DMODEL],   g_o1l [MROWS*DMODEL];
__device__ bf16  g_h1h [MROWS*DFF],      g_h1l [MROWS*DFF];
__device__ float g_ffn [MROWS*DMODEL];   // split-K partial 0 (FFN2)

// ------------------------------ PTX helpers ---------------------------------
__device__ __forceinline__ uint32_t smem_u32(const void* p) {
    uint32_t a;
    asm("{ .reg .u64 t; cvta.to.shared.u64 t, %1; cvt.u32.u64 %0, t; }"
        : "=r"(a) : "l"(p));
    return a;
}

#define CP16(dst, src) \
    asm volatile("cp.async.cg.shared.global [%0], [%1], 16;" \
                 :: "r"(dst), "l"(src))
#define CP_COMMIT() asm volatile("cp.async.commit_group;" ::: "memory")
#define CP_WAIT(n)  asm volatile("cp.async.wait_group %0;" :: "n"(n) : "memory")

#define LDM_X4(r, a) \
    asm volatile("ldmatrix.sync.aligned.m8n8.x4.shared.b16 {%0,%1,%2,%3}, [%4];" \
        : "=r"((r)[0]), "=r"((r)[1]), "=r"((r)[2]), "=r"((r)[3]) : "r"(a))

#define LDM_X4T(r, a) \
    asm volatile("ldmatrix.sync.aligned.m8n8.x4.trans.shared.b16 {%0,%1,%2,%3}, [%4];" \
        : "=r"((r)[0]), "=r"((r)[1]), "=r"((r)[2]), "=r"((r)[3]) : "r"(a))

#define MMA16816(d, a, b0, b1) \
    asm volatile("mma.sync.aligned.m16n8k16.row.col.f32.bf16.bf16.f32 " \
        "{%0,%1,%2,%3}, {%4,%5,%6,%7}, {%8,%9}, {%0,%1,%2,%3};" \
        : "+f"((d)[0]), "+f"((d)[1]), "+f"((d)[2]), "+f"((d)[3]) \
        : "r"((a)[0]), "r"((a)[1]), "r"((a)[2]), "r"((a)[3]), "r"(b0), "r"(b1))

__device__ __forceinline__ void split2(float x, float y, uint32_t& hp, uint32_t& lp) {
    __nv_bfloat162 h = __float22bfloat162_rn(make_float2(x, y));
    float2 r = make_float2(x - __bfloat162float(h.x), y - __bfloat162float(h.y));
    __nv_bfloat162 l = __float22bfloat162_rn(r);
    hp = *(uint32_t*)&h;
    lp = *(uint32_t*)&l;
}

// ---------------------- HMMA GEMM: C = A @ B^T + bias -----------------------
// CTA tile BM=128 x BN=256, BK=64. 256 threads = 8 warps (2 x 4),
// warp tile 64x64. Swizzled 128B-row smem (seg ^= row&7). B-register reuse.
// Split-K via gridDim.z (EPI==0 only): kz=0 -> Cf (+bias), kz=1 -> Cf2,
// kz=2 -> Cf3; reduction fused into add_ln4.
// EPI: 0 = fp32 [M,N]; 2 = ReLU + bf16 hi/lo [M,N]; 3 = QKV bf16 hi/lo scatter.
#define GA_BYTES 16384               // one A array: 128 rows x 128 B
#define GB_BYTES 32768               // one B array: 256 rows x 128 B
#define GSTG     (2*GA_BYTES + 2*GB_BYTES)   // 98304 B per stage
#define GSMEM    (2 * GSTG)                  // 196608 B

template<int EPI>
__global__ void __launch_bounds__(256, 1)
mma_gemm(const bf16* __restrict__ Ah_, const bf16* __restrict__ Al_,
         const bf16* __restrict__ Bh_, const bf16* __restrict__ Bl_,
         const float* __restrict__ bias,
         float* __restrict__ Cf, float* __restrict__ Cf2, float* __restrict__ Cf3,
         bf16* __restrict__ Ch, bf16* __restrict__ Cl,
         int N, int K)
{
    extern __shared__ __align__(128) char smem[];
    const uint32_t sb = smem_u32(smem);
    const int tid  = threadIdx.x;
    const int lane = tid & 31;
    const int wid  = tid >> 5;
    const int wm   = wid >> 2;            // 0..1  (64-row band)
    const int wn   = wid & 3;             // 0..3  (64-col band)
    const int row0 = blockIdx.y * 128, col0 = blockIdx.x * 256;
    const int kz   = blockIdx.z;
    const int Kp   = K / (int)gridDim.z;  // K per slice
    const int kbeg = kz * Kp;
    const int NT   = Kp >> 6;             // BK = 64

    float acc[4][8][4];
#pragma unroll
    for (int i = 0; i < 4; i++)
#pragma unroll
        for (int j = 0; j < 8; j++)
#pragma unroll
            for (int r = 0; r < 4; r++) acc[i][j][r] = 0.f;

    auto load_stage = [&](int kt, int stg) {
        const int k0 = kbeg + (kt << 6);
        const uint32_t sd = sb + stg * GSTG;
#pragma unroll
        for (int c = tid; c < 6144; c += 256) {
            if (c < 2048) {               // A arrays
                const int arr = c >> 10, rem = c & 1023;
                const int r = rem >> 3, seg = rem & 7;
                const uint32_t d = sd + arr * GA_BYTES + r * 128
                                 + ((seg ^ (r & 7)) << 4);
                const bf16* s = (arr ? Al_ : Ah_) + (size_t)(row0 + r) * K + k0 + seg * 8;
                CP16(d, s);
            } else {                      // B arrays
                const int cc = c - 2048;
                const int arr = cc >> 11, rem = cc & 2047;
                const int r = rem >> 3, seg = rem & 7;
                const uint32_t d = sd + 2 * GA_BYTES + arr * GB_BYTES + r * 128
                                 + ((seg ^ (r & 7)) << 4);
                const bf16* s = (arr ? Bl_ : Bh_) + (size_t)(col0 + r) * K + k0 + seg * 8;
                CP16(d, s);
            }
        }
    };

    load_stage(0, 0); CP_COMMIT();

    for (int kt = 0; kt < NT; kt++) {
        CP_WAIT(0);
        __syncthreads();
        if (kt + 1 < NT) {
            load_stage(kt + 1, (kt + 1) & 1);
            CP_COMMIT();
        }

        const uint32_t sA = sb + (kt & 1) * GSTG;
        const uint32_t sB = sA + 2 * GA_BYTES;
#pragma unroll
        for (int kc = 0; kc < 4; kc++) {   // four K16 slices
            uint32_t ah[4][4], al[4][4], b[4][4];
            uint32_t baddr[4];
#pragma unroll
            for (int mt = 0; mt < 4; mt++) {
                const int row = wm * 64 + mt * 16 + (lane & 15);
                const int seg = kc * 2 + (lane >> 4);
                const uint32_t a = sA + (uint32_t)(row * 128 + ((seg ^ (row & 7)) << 4));
                LDM_X4(ah[mt], a);
                LDM_X4(al[mt], a + GA_BYTES);
            }
#pragma unroll
            for (int g = 0; g < 4; g++) {
                const int row = wn * 64 + g * 16 + ((lane >> 4) << 3) + (lane & 7);
                const int seg = kc * 2 + ((lane >> 3) & 1);
                baddr[g] = sB + (uint32_t)(row * 128 + ((seg ^ (row & 7)) << 4));
                LDM_X4(b[g], baddr[g]);             // Bh
            }
            // terms 1 + 3 use Bh
#pragma unroll
            for (int mt = 0; mt < 4; mt++)
#pragma unroll
                for (int nt = 0; nt < 8; nt++) {
                    const int g = nt >> 1, o = (nt & 1) * 2;
                    MMA16816(acc[mt][nt], ah[mt], b[g][o], b[g][o + 1]);
                }
#pragma unroll
            for (int mt = 0; mt < 4; mt++)
#pragma unroll
                for (int nt = 0; nt < 8; nt++) {
                    const int g = nt >> 1, o = (nt & 1) * 2;
                    MMA16816(acc[mt][nt], al[mt], b[g][o], b[g][o + 1]);
                }
            // reload same registers with Bl, term 2
#pragma unroll
            for (int g = 0; g < 4; g++)
                LDM_X4(b[g], baddr[g] + GB_BYTES);  // Bl
#pragma unroll
            for (int mt = 0; mt < 4; mt++)
#pragma unroll
                for (int nt = 0; nt < 8; nt++) {
                    const int g = nt >> 1, o = (nt & 1) * 2;
                    MMA16816(acc[mt][nt], ah[mt], b[g][o], b[g][o + 1]);
                }
        }
    }

    // ---- epilogue straight from registers ----
    float* dst = Cf;
    if (EPI == 0) dst = (kz == 0) ? Cf : (kz == 1 ? Cf2 : Cf3);
#pragma unroll
    for (int mt = 0; mt < 4; mt++) {
#pragma unroll
        for (int nt = 0; nt < 8; nt++) {
            const int row = row0 + wm * 64 + mt * 16 + (lane >> 2);
            const int col = col0 + wn * 64 + nt * 8 + (lane & 3) * 2;
            const bool wbias = (EPI != 0) || (kz == 0);
            const float b0 = wbias ? __ldg(bias + col)     : 0.f;
            const float b1 = wbias ? __ldg(bias + col + 1) : 0.f;
#pragma unroll
            for (int half = 0; half < 2; half++) {
                const int rr = row + half * 8;
                float v0 = acc[mt][nt][half * 2]     + b0;
                float v1 = acc[mt][nt][half * 2 + 1] + b1;
                if (EPI == 0) {
                    *(float2*)&dst[(size_t)rr * N + col] = make_float2(v0, v1);
                } else if (EPI == 2) {
                    v0 = fmaxf(v0, 0.f); v1 = fmaxf(v1, 0.f);
                    uint32_t hp, lp;
                    split2(v0, v1, hp, lp);
                    *(uint32_t*)&Ch[(size_t)rr * N + col] = hp;
                    *(uint32_t*)&Cl[(size_t)rr * N + col] = lp;
                } else {  // EPI==3: QKV scatter [which][b,h,s,d], Q pre-scaled
                    const int which = col / DMODEL;
                    const int cc = col - which * DMODEL;
                    const int h = cc >> 6, d = cc & 63;
                    if (which == 0) { v0 *= 0.125f; v1 *= 0.125f; }
                    const int b_ = rr >> 10, s = rr & 1023;
                    const size_t dsti = (size_t)which * MROWS * DMODEL
                        + (((size_t)(b_ * NHEADS + h)) * SEQ + s) * DHEAD + d;
                    uint32_t hp, lp;
                    split2(v0, v1, hp, lp);
                    *(uint32_t*)&Ch[dsti] = hp;
                    *(uint32_t*)&Cl[dsti] = lp;
                }
            }
        }
    }
}

// ---------------------- flash attention (HMMA bf16 3-split) ------------------
// BQ=128, BK=64. 256 threads = 8 warps (r14-proven configuration).
#define ASTR   72
#define QTILE  (128 * ASTR * 2)       // 18432 B per Q array
#define KVTILE (64 * ASTR * 2)        // 9216 B per KV array
#define AKVST  (4 * KVTILE)           // 36864 B per stage
#define ATT_SMEM (2 * QTILE + 2 * AKVST)   // 110592 B

__global__ void __launch_bounds__(256, 1)
attn_mma(const bf16* __restrict__ QKVh, const bf16* __restrict__ QKVl,
         bf16* __restrict__ ch, bf16* __restrict__ cl)
{
    extern __shared__ __align__(128) char smem[];
    const uint32_t sb = smem_u32(smem);
    const int tid = threadIdx.x, lane = tid & 31, wid = tid >> 5;
    const int qt = blockIdx.x, bh = blockIdx.y, q0 = qt * 128;
    const int NKT = 2 * qt + 2;
    constexpr size_t MD = (size_t)MROWS * DMODEL;
    const bf16 *Qh = QKVh,        *Kh = QKVh + MD, *Vh = QKVh + 2 * MD;
    const bf16 *Ql = QKVl,        *Kl = QKVl + MD, *Vl = QKVl + 2 * MD;
    const size_t hb = (size_t)bh * SEQ * DHEAD;

    auto load_kv = [&](int kt, int stg) {
        const size_t gb = hb + (size_t)(kt * 64) * 64;
        const uint32_t sd = sb + 2 * QTILE + stg * AKVST;
        for (int i = tid; i < 512; i += 256) {
            const int row = i >> 3, seg = i & 7;
            const uint32_t d0 = sd + row * 144 + seg * 16;
            const size_t g = gb + row * 64 + seg * 8;
            CP16(d0,              Kh + g);
            CP16(d0 + KVTILE,     Kl + g);
            CP16(d0 + 2 * KVTILE, Vh + g);
            CP16(d0 + 3 * KVTILE, Vl + g);
        }
    };

    {   // Q tiles (128 rows) + stage0
        const size_t gq = hb + (size_t)q0 * 64;
        for (int i = tid; i < 1024; i += 256) {
            const int row = i >> 3, seg = i & 7;
            const uint32_t d0 = sb + row * 144 + seg * 16;
            const size_t g = gq + row * 64 + seg * 8;
            CP16(d0,         Qh + g);
            CP16(d0 + QTILE, Ql + g);
        }
        load_kv(0, 0);
    }
    CP_COMMIT();
    load_kv(1, 1);
    CP_COMMIT();

    uint32_t qh[4][4], ql[4][4];
    float oacc[8][4];
#pragma unroll
    for (int nt = 0; nt < 8; nt++)
#pragma unroll
        for (int e = 0; e < 4; e++) oacc[nt][e] = 0.f;
    float m0 = -1e30f, m1 = -1e30f, l0 = 0.f, l1 = 0.f;

    const int lcol  = (lane & 3) * 2;
    const int rowg0 = q0 + wid * 16 + (lane >> 2);
    const int wrow_max = q0 + wid * 16 + 15;

    for (int kt = 0; kt < NKT; kt++) {
        CP_WAIT(1);
        __syncthreads();
        if (kt == 0) {
#pragma unroll
            for (int kc = 0; kc < 4; kc++) {
                const uint32_t a = sb + (uint32_t)(((wid * 16 + (lane & 15)) * ASTR
                                    + ((lane >> 4) << 3) + kc * 16) * 2);
                LDM_X4(qh[kc], a);
                LDM_X4(ql[kc], a + QTILE);
            }
        }
        const bool active = (kt * 64 <= wrow_max);
        const uint32_t kvb = sb + 2 * QTILE + (kt & 1) * AKVST;

        if (active) {
            float sacc[8][4];
#pragma unroll
            for (int nt = 0; nt < 8; nt++)
#pragma unroll
                for (int e = 0; e < 4; e++) sacc[nt][e] = 0.f;

#pragma unroll
            for (int kc = 0; kc < 4; kc++) {
                uint32_t kh2[8][2], kl2[8][2];
#pragma unroll
                for (int g = 0; g < 4; g++) {
                    const uint32_t a = kvb + (uint32_t)(((g * 16 + ((lane >> 4) << 3)
                        + (lane & 7)) * ASTR + (((lane >> 3) & 1) << 3) + kc * 16) * 2);
                    uint32_t r[4];
                    LDM_X4(r, a);
                    kh2[2*g][0]=r[0]; kh2[2*g][1]=r[1]; kh2[2*g+1][0]=r[2]; kh2[2*g+1][1]=r[3];
                    LDM_X4(r, a + KVTILE);
                    kl2[2*g][0]=r[0]; kl2[2*g][1]=r[1]; kl2[2*g+1][0]=r[2]; kl2[2*g+1][1]=r[3];
                }
#pragma unroll
                for (int nt = 0; nt < 8; nt++)
                    MMA16816(sacc[nt], qh[kc], kh2[nt][0], kh2[nt][1]);
#pragma unroll
                for (int nt = 0; nt < 8; nt++)
                    MMA16816(sacc[nt], qh[kc], kl2[nt][0], kl2[nt][1]);
#pragma unroll
                for (int nt = 0; nt < 8; nt++)
                    MMA16816(sacc[nt], ql[kc], kh2[nt][0], kh2[nt][1]);
            }

            if (kt * 64 + 63 > rowg0) {
#pragma unroll
                for (int nt = 0; nt < 8; nt++) {
                    const int colb = kt * 64 + nt * 8 + lcol;
                    if (colb     > rowg0)     sacc[nt][0] = -1e30f;
                    if (colb + 1 > rowg0)     sacc[nt][1] = -1e30f;
                    if (colb     > rowg0 + 8) sacc[nt][2] = -1e30f;
                    if (colb + 1 > rowg0 + 8) sacc[nt][3] = -1e30f;
                }
            }

            float tm0 = -1e30f, tm1 = -1e30f;
#pragma unroll
            for (int nt = 0; nt < 8; nt++) {
                tm0 = fmaxf(tm0, fmaxf(sacc[nt][0], sacc[nt][1]));
                tm1 = fmaxf(tm1, fmaxf(sacc[nt][2], sacc[nt][3]));
            }
            tm0 = fmaxf(tm0, __shfl_xor_sync(0xffffffffu, tm0, 1));
            tm0 = fmaxf(tm0, __shfl_xor_sync(0xffffffffu, tm0, 2));
            tm1 = fmaxf(tm1, __shfl_xor_sync(0xffffffffu, tm1, 1));
            tm1 = fmaxf(tm1, __shfl_xor_sync(0xffffffffu, tm1, 2));

            const float mn0 = fmaxf(m0, tm0), mn1 = fmaxf(m1, tm1);
            const float a0 = __expf(m0 - mn0), a1 = __expf(m1 - mn1);
            m0 = mn0; m1 = mn1;

            float s0 = 0.f, s1 = 0.f;
#pragma unroll
            for (int nt = 0; nt < 8; nt++) {
                sacc[nt][0] = __expf(sacc[nt][0] - mn0); s0 += sacc[nt][0];
                sacc[nt][1] = __expf(sacc[nt][1] - mn0); s0 += sacc[nt][1];
                sacc[nt][2] = __expf(sacc[nt][2] - mn1); s1 += sacc[nt][2];
                sacc[nt][3] = __expf(sacc[nt][3] - mn1); s1 += sacc[nt][3];
            }
            s0 += __shfl_xor_sync(0xffffffffu, s0, 1);
            s0 += __shfl_xor_sync(0xffffffffu, s0, 2);
            s1 += __shfl_xor_sync(0xffffffffu, s1, 1);
            s1 += __shfl_xor_sync(0xffffffffu, s1, 2);
            l0 = l0 * a0 + s0;
            l1 = l1 * a1 + s1;
#pragma unroll
            for (int nt = 0; nt < 8; nt++) {
                oacc[nt][0] *= a0; oacc[nt][1] *= a0;
                oacc[nt][2] *= a1; oacc[nt][3] *= a1;
            }

            const uint32_t vb = kvb + 2 * KVTILE;
#pragma unroll
            for (int j = 0; j < 4; j++) {
                uint32_t vh2[8][2], vl2[8][2];
#pragma unroll
                for (int ng = 0; ng < 4; ng++) {
                    const uint32_t a = vb + (uint32_t)(((j * 16 + (lane & 15)) * ASTR
                                        + ng * 16 + ((lane >> 4) << 3)) * 2);
                    uint32_t r[4];
                    LDM_X4T(r, a);
                    vh2[2*ng][0]=r[0]; vh2[2*ng][1]=r[1]; vh2[2*ng+1][0]=r[2]; vh2[2*ng+1][1]=r[3];
                    LDM_X4T(r, a + KVTILE);
                    vl2[2*ng][0]=r[0]; vl2[2*ng][1]=r[1]; vl2[2*ng+1][0]=r[2]; vl2[2*ng+1][1]=r[3];
                }
                uint32_t ph[4], pl[4];
                split2(sacc[2*j][0],   sacc[2*j][1],   ph[0], pl[0]);
                split2(sacc[2*j][2],   sacc[2*j][3],   ph[1], pl[1]);
                split2(sacc[2*j+1][0], sacc[2*j+1][1], ph[2], pl[2]);
                split2(sacc[2*j+1][2], sacc[2*j+1][3], ph[3], pl[3]);
#pragma unroll
                for (int nt = 0; nt < 8; nt++)
                    MMA16816(oacc[nt], ph, vh2[nt][0], vh2[nt][1]);
#pragma unroll
                for (int nt = 0; nt < 8; nt++)
                    MMA16816(oacc[nt], ph, vl2[nt][0], vl2[nt][1]);
#pragma unroll
                for (int nt = 0; nt < 8; nt++)
                    MMA16816(oacc[nt], pl, vh2[nt][0], vh2[nt][1]);
            }
        }
        __syncthreads();
        if (kt + 2 < NKT) load_kv(kt + 2, kt & 1);
        CP_COMMIT();
    }

    const float i0 = 1.f / l0, i1 = 1.f / l1;
    const int b_ = bh / NHEADS, h = bh % NHEADS;
#pragma unroll
    for (int nt = 0; nt < 8; nt++) {
        const int d = nt * 8 + lcol;
        const size_t r0i = ((size_t)(b_ * SEQ + rowg0)) * DMODEL + h * 64 + d;
        const size_t r1i = r0i + (size_t)8 * DMODEL;
        uint32_t hp, lp;
        split2(oacc[nt][0] * i0, oacc[nt][1] * i0, hp, lp);
        *(uint32_t*)&ch[r0i] = hp;
        *(uint32_t*)&cl[r0i] = lp;
        split2(oacc[nt][2] * i1, oacc[nt][3] * i1, hp, lp);
        *(uint32_t*)&ch[r1i] = hp;
        *(uint32_t*)&cl[r1i] = lp;
    }
}

// ---------------------- prep kernels ----------------------------------------
__global__ void __launch_bounds__(256)
split_kernel(const float* __restrict__ src, bf16* __restrict__ hi,
             bf16* __restrict__ lo, int n)
{
    int i0 = (blockIdx.x * 256 + threadIdx.x) * 4;
    if (i0 >= n) return;
#pragma unroll
    for (int j = 0; j < 4; j++) {
        float v = src[i0 + j];
        bf16 h = __float2bfloat16(v);
        hi[i0 + j] = h;
        lo[i0 + j] = __float2bfloat16(v - __bfloat162float(h));
    }
}

// Fused transpose+split of ALL weights: src[K,N] -> dst[N,K] bf16 hi/lo.
__global__ void __launch_bounds__(256)
prep_weights(const float* __restrict__ wq, const float* __restrict__ wk,
             const float* __restrict__ wv, const float* __restrict__ wo,
             const float* __restrict__ w1, const float* __restrict__ w2,
             bf16* __restrict__ wqkvh, bf16* __restrict__ wqkvl,
             bf16* __restrict__ woh,   bf16* __restrict__ wol,
             bf16* __restrict__ w1h,   bf16* __restrict__ w1l,
             bf16* __restrict__ w2h,   bf16* __restrict__ w2l)
{
    int b = blockIdx.x;
    const float* src; bf16 *dh, *dl; int K, N;
    if (b < 1728) {
        const int w = b / 576; b -= w * 576;
        src = (w == 0) ? wq : (w == 1 ? wk : wv);
        dh = wqkvh + (size_t)w * DMODEL * DMODEL;
        dl = wqkvl + (size_t)w * DMODEL * DMODEL;
        K = DMODEL; N = DMODEL;
    } else if (b < 2304) { b -= 1728; src = wo; dh = woh; dl = wol; K = DMODEL; N = DMODEL; }
    else if (b < 4608)   { b -= 2304; src = w1; dh = w1h; dl = w1l; K = DMODEL; N = DFF; }
    else                 { b -= 4608; src = w2; dh = w2h; dl = w2l; K = DFF; N = DMODEL; }

    const int nb = N / 32;
    const int bx = (b % nb) * 32;
    const int by = (b / nb) * 32;
    __shared__ float t[32][33];
    const int tx = threadIdx.x & 31, ty = threadIdx.x >> 5;
#pragma unroll
    for (int i = 0; i < 32; i += 8)
        t[ty + i][tx] = src[(size_t)(by + ty + i) * N + bx + tx];
    __syncthreads();
#pragma unroll
    for (int i = 0; i < 32; i += 8) {
        float v = t[tx][ty + i];
        bf16 h = __float2bfloat16(v);
        size_t o = (size_t)(bx + ty + i) * K + by + tx;
        dh[o] = h;
        dl[o] = __float2bfloat16(v - __bfloat162float(h));
    }
}

__global__ void __launch_bounds__(256)
concat_bias(const float* __restrict__ bq, const float* __restrict__ bk,
            const float* __restrict__ bv, float* __restrict__ out)
{
    int i = blockIdx.x * 256 + threadIdx.x;
    if (i >= 3 * DMODEL) return;
    out[i] = i < DMODEL ? bq[i] : (i < 2 * DMODEL ? bk[i - DMODEL] : bv[i - 2 * DMODEL]);
}

// ------------ fused residual add + split-K(3) reduce + LayerNorm ------------
// out = LN(a + p0 + p1 + p2), optional bf16 hi/lo output.
template<bool HILO>
__global__ void __launch_bounds__(256)
add_ln4_kernel(const float* __restrict__ a, const float* __restrict__ p0,
               const float* __restrict__ p1, const float* __restrict__ p2,
               const float* __restrict__ g, const float* __restrict__ be,
               float* __restrict__ out, bf16* __restrict__ ohi, bf16* __restrict__ olo)
{
    __shared__ float red[8];
    const int row = blockIdx.x;
    const int t   = threadIdx.x;
    const float* ar = a  + (size_t)row * DMODEL;
    const float* b0 = p0 + (size_t)row * DMODEL;
    const float* b1 = p1 + (size_t)row * DMODEL;
    const float* b2 = p2 + (size_t)row * DMODEL;

    float v0 = ar[t]       + b0[t]       + b1[t]       + b2[t];
    float v1 = ar[t + 256] + b0[t + 256] + b1[t + 256] + b2[t + 256];
    float v2 = ar[t + 512] + b0[t + 512] + b1[t + 512] + b2[t + 512];

    float sum = v0 + v1 + v2;
#pragma unroll
    for (int off = 16; off; off >>= 1) sum += __shfl_xor_sync(0xffffffffu, sum, off);
    if ((t & 31) == 0) red[t >> 5] = sum;
    __syncthreads();
    float tot = 0.f;
#pragma unroll
    for (int w = 0; w < 8; w++) tot += red[w];
    const float mu = tot * (1.f / DMODEL);
    __syncthreads();

    float d0 = v0 - mu, d1 = v1 - mu, d2 = v2 - mu;
    float vs = d0 * d0 + d1 * d1 + d2 * d2;
#pragma unroll
    for (int off = 16; off; off >>= 1) vs += __shfl_xor_sync(0xffffffffu, vs, off);
    if ((t & 31) == 0) red[t >> 5] = vs;
    __syncthreads();
    tot = 0.f;
#pragma unroll
    for (int w = 0; w < 8; w++) tot += red[w];
    const float rstd = rsqrtf(tot * (1.f / DMODEL) + 1e-6f);

    float* o = out + (size_t)row * DMODEL;
    float r0 = g[t]       * d0 * rstd + be[t];
    float r1 = g[t + 256] * d1 * rstd + be[t + 256];
    float r2 = g[t + 512] * d2 * rstd + be[t + 512];
    o[t] = r0; o[t + 256] = r1; o[t + 512] = r2;
    if (HILO) {
        size_t base = (size_t)row * DMODEL;
#pragma unroll
        for (int j = 0; j < 3; j++) {
            float v = j == 0 ? r0 : (j == 1 ? r1 : r2);
            int idx = t + j * 256;
            bf16 h = __float2bfloat16(v);
            ohi[base + idx] = h;
            olo[base + idx] = __float2bfloat16(v - __bfloat162float(h));
        }
    }
}

// --------------------------------- launch ------------------------------------
extern "C" void kernel_launch(void* const* d_in, const int* in_sizes, int n_in,
                              void* d_out, int out_size)
{
    const float* x  = (const float*)d_in[0];
    const float* wq = (const float*)d_in[2];
    const float* bq = (const float*)d_in[3];
    const float* wk = (const float*)d_in[4];
    const float* bk = (const float*)d_in[5];
    const float* wv = (const float*)d_in[6];
    const float* bv = (const float*)d_in[7];
    const float* wo = (const float*)d_in[8];
    const float* bo = (const float*)d_in[9];
    const float* w1 = (const float*)d_in[10];
    const float* b1 = (const float*)d_in[11];
    const float* w2 = (const float*)d_in[12];
    const float* b2 = (const float*)d_in[13];
    const float* g1 = (const float*)d_in[14];
    const float* be1= (const float*)d_in[15];
    const float* g2 = (const float*)d_in[16];
    const float* be2= (const float*)d_in[17];
    float* out = (float*)d_out;

    bf16 *xh,*xl,*wqkvh,*wqkvl,*woh,*wol,*w1h,*w1l,*w2h,*w2l;
    bf16 *qkvh,*qkvl,*ch,*cl,*o1h,*o1l,*h1h,*h1l;
    float *bqkv,*attn,*p2,*p3,*out1,*ffn;
    cudaGetSymbolAddress((void**)&xh,   g_xh);    cudaGetSymbolAddress((void**)&xl,   g_xl);
    cudaGetSymbolAddress((void**)&wqkvh,g_wqkvh); cudaGetSymbolAddress((void**)&wqkvl,g_wqkvl);
    cudaGetSymbolAddress((void**)&woh,  g_woh);   cudaGetSymbolAddress((void**)&wol,  g_wol);
    cudaGetSymbolAddress((void**)&w1h,  g_w1h);   cudaGetSymbolAddress((void**)&w1l,  g_w1l);
    cudaGetSymbolAddress((void**)&w2h,  g_w2h);   cudaGetSymbolAddress((void**)&w2l,  g_w2l);
    cudaGetSymbolAddress((void**)&bqkv, g_bqkv);
    cudaGetSymbolAddress((void**)&qkvh, g_qkvh);  cudaGetSymbolAddress((void**)&qkvl, g_qkvl);
    cudaGetSymbolAddress((void**)&ch,   g_ch);    cudaGetSymbolAddress((void**)&cl,   g_cl);
    cudaGetSymbolAddress((void**)&o1h,  g_o1h);   cudaGetSymbolAddress((void**)&o1l,  g_o1l);
    cudaGetSymbolAddress((void**)&h1h,  g_h1h);   cudaGetSymbolAddress((void**)&h1l,  g_h1l);
    cudaGetSymbolAddress((void**)&attn, g_attn);  cudaGetSymbolAddress((void**)&p2,   g_p2);
    cudaGetSymbolAddress((void**)&p3,   g_p3);
    cudaGetSymbolAddress((void**)&out1, g_out1);  cudaGetSymbolAddress((void**)&ffn,  g_ffn);

    cudaFuncSetAttribute(mma_gemm<0>, cudaFuncAttributeMaxDynamicSharedMemorySize, GSMEM);
    cudaFuncSetAttribute(mma_gemm<2>, cudaFuncAttributeMaxDynamicSharedMemorySize, GSMEM);
    cudaFuncSetAttribute(mma_gemm<3>, cudaFuncAttributeMaxDynamicSharedMemorySize, GSMEM);
    cudaFuncSetAttribute(attn_mma,    cudaFuncAttributeMaxDynamicSharedMemorySize, ATT_SMEM);

    // ---- prep ----
    split_kernel<<<MROWS * DMODEL / 1024, 256>>>(x, xh, xl, MROWS * DMODEL);   // #1
    prep_weights<<<6912, 256>>>(wq, wk, wv, wo, w1, w2,
                                wqkvh, wqkvl, woh, wol, w1h, w1l, w2h, w2l);   // #2
    concat_bias<<<(3*DMODEL + 255)/256, 256>>>(bq, bk, bv, bqkv);              // #3

    // ---- fused QKV (N=2304), epilogue -> bf16 hi/lo head layout ----
    mma_gemm<3><<<dim3(3*DMODEL/256, MROWS/128), 256, GSMEM>>>(
        xh, xl, wqkvh, wqkvl, bqkv, nullptr, nullptr, nullptr, qkvh, qkvl,
        3*DMODEL, DMODEL);                                                     // #4

    // ---- flash attention (BQ=128) ----
    attn_mma<<<dim3(SEQ/128, BATCH*NHEADS), 256, ATT_SMEM>>>(qkvh, qkvl, ch, cl); // #5

    // ---- O proj: split-K=3 (partials attn, p2, p3) + LN1 reduce ----
    mma_gemm<0><<<dim3(DMODEL/256, MROWS/128, 3), 256, GSMEM>>>(
        ch, cl, woh, wol, bo, attn, p2, p3, nullptr, nullptr, DMODEL, DMODEL); // #6
    add_ln4_kernel<true><<<MROWS, 256>>>(x, attn, p2, p3, g1, be1, out1, o1h, o1l);

    // ---- FFN ----
    mma_gemm<2><<<dim3(DFF/256, MROWS/128), 256, GSMEM>>>(o1h, o1l, w1h, w1l, b1,
                                                          nullptr, nullptr, nullptr,
                                                          h1h, h1l, DFF, DMODEL);
    // FFN2: split-K=3 (partials ffn, p2, p3) + LN2 reduce
    mma_gemm<0><<<dim3(DMODEL/256, MROWS/128, 3), 256, GSMEM>>>(
        h1h, h1l, w2h, w2l, b2, ffn, p2, p3, nullptr, nullptr, DMODEL, DFF);
    add_ln4_kernel<false><<<MROWS, 256>>>(out1, ffn, p2, p3, g2, be2, out, nullptr, nullptr);
}